// round 4
// baseline (speedup 1.0000x reference)
#include <cuda_runtime.h>

// Resample2d (FlowNet2 bilinear warp), fixed shape B=4, C=64, H=384, W=512.
//
// R3: shared-memory tiled gather.
//   Block = 64x16 output pixels (256 threads, 4 rows per thread).
//   Per channel: stage a 28x80 input tile (halo: rows -6..+21 rel. to tile top,
//   cols -8..+71) into smem with coalesced scalar loads, then do the 4 bilinear
//   taps as cheap LDS. Taps that fall outside the tile (|flow| beyond the halo,
//   astronomically rare for N(0,1) flow, or heavy border clamping from a
//   non-border block) use a predicated global-memory fallback for exactness.

static constexpr int B = 4;
static constexpr int C = 64;
static constexpr int H = 384;
static constexpr int W = 512;
static constexpr int HW = H * W;

static constexpr int TX = 64;        // output tile width
static constexpr int TY = 16;        // output tile height
static constexpr int HALO_UP = 6;    // rows above
static constexpr int TROWS = 28;     // 16 + 6 up + 6 down
static constexpr int HALO_L = 8;     // cols left
static constexpr int TCOLS = 80;     // 64 + 8 left + 8 right
static constexpr int TS = 81;        // padded row stride (odd -> bank spread)
static constexpr int TELEMS = TROWS * TS;          // 2268
static constexpr int FILL_IT = (TELEMS + 255) / 256; // 9

__device__ __forceinline__ int iclamp(int v, int lo, int hi) {
    return min(max(v, lo), hi);
}

__global__ __launch_bounds__(256, 5) void resample2d_kernel(
    const float* __restrict__ in1,
    const float* __restrict__ flow,
    float* __restrict__ out)
{
    __shared__ float tile[TELEMS];

    int tid = threadIdx.x;
    int xb = blockIdx.x * TX;
    int yb = blockIdx.y * TY;
    int bz = blockIdx.z;

    int x  = xb + (tid & 63);
    int ry = tid >> 6;               // 0..3

    // ---- precompute clamped global source indices for the tile fill ----
    int sidx[FILL_IT];
    #pragma unroll
    for (int k = 0; k < FILL_IT; ++k) {
        int e = tid + k * 256;
        int r  = e / TS;
        int cc = e - r * TS;
        int gy = iclamp(yb - HALO_UP + r, 0, H - 1);
        int gx = iclamp(xb - HALO_L + cc, 0, W - 1);
        sidx[k] = (e < TELEMS) ? (gy * W + gx) : 0;
    }

    // ---- per-pixel flow preamble (4 pixels per thread) ----
    float fa[4], fbw[4];
    unsigned pk0[4], pk1[4];
    int fbmask = 0;
    int opix0 = (yb + ry) * W + x;   // pixel p is at opix0 + p*4*W

    const float* fptr = flow + (size_t)bz * 2 * HW;
    #pragma unroll
    for (int p = 0; p < 4; ++p) {
        int y   = yb + ry + 4 * p;
        int pix = y * W + x;
        float dx = fptr[pix];
        float dy = fptr[HW + pix];

        float xf = (float)x + dx;
        float yf = (float)y + dy;
        float x0f = floorf(xf);
        float y0f = floorf(yf);
        fa[p]  = xf - x0f;
        fbw[p] = yf - y0f;

        int x0i = (int)x0f;
        int y0i = (int)y0f;
        int x0 = iclamp(x0i,     0, W - 1);
        int x1 = iclamp(x0i + 1, 0, W - 1);
        int y0 = iclamp(y0i,     0, H - 1);
        int y1 = iclamp(y0i + 1, 0, H - 1);

        int tc0 = x0 - (xb - HALO_L);
        int tc1 = x1 - (xb - HALO_L);
        int tr0 = y0 - (yb - HALO_UP);
        int tr1 = y1 - (yb - HALO_UP);

        bool ok = (tc0 >= 0) & (tc1 < TCOLS) & (tr0 >= 0) & (tr1 < TROWS);
        if (ok) {
            pk0[p] = (unsigned)(tr0 * TS + tc0) | ((unsigned)(tr0 * TS + tc1) << 16);
            pk1[p] = (unsigned)(tr1 * TS + tc0) | ((unsigned)(tr1 * TS + tc1) << 16);
        } else {
            fbmask |= 1 << p;
            pk0[p] = (unsigned)(y0 * W + x0);                     // global base
            pk1[p] = (unsigned)(x1 - x0) | ((unsigned)(y1 - y0) << 1); // dxi, dyi
        }
    }

    const float* bin  = in1 + (size_t)bz * C * HW;
    float*       bout = out + (size_t)bz * C * HW;

    for (int c = 0; c < C; ++c) {
        const float* src = bin + (size_t)c * HW;

        // fill tile (coalesced scalar loads)
        #pragma unroll
        for (int k = 0; k < FILL_IT; ++k) {
            int e = tid + k * 256;
            if (e < TELEMS) tile[e] = __ldg(src + sidx[k]);
        }
        __syncthreads();

        // gather + store 4 pixels
        float* dst = bout + (size_t)c * HW;
        #pragma unroll
        for (int p = 0; p < 4; ++p) {
            float a  = fa[p];
            float bw = fbw[p];
            float w00 = (1.0f - a) * (1.0f - bw);
            float w10 = a * (1.0f - bw);
            float w01 = (1.0f - a) * bw;
            float w11 = a * bw;

            float res;
            if (!((fbmask >> p) & 1)) {
                int t00 = pk0[p] & 0xffff;
                int t10 = pk0[p] >> 16;
                int t01 = pk1[p] & 0xffff;
                int t11 = pk1[p] >> 16;
                res = w00 * tile[t00] + w10 * tile[t10]
                    + w01 * tile[t01] + w11 * tile[t11];
            } else {
                int g00 = (int)pk0[p];
                int dxi = pk1[p] & 1;
                int dyi = (pk1[p] >> 1) & 1;
                const float* gp = src + g00;
                res = w00 * __ldg(gp)
                    + w10 * __ldg(gp + dxi)
                    + w01 * __ldg(gp + dyi * W)
                    + w11 * __ldg(gp + dyi * W + dxi);
            }
            dst[opix0 + p * 4 * W] = res;
        }
        __syncthreads();
    }
}

extern "C" void kernel_launch(void* const* d_in, const int* in_sizes, int n_in,
                              void* d_out, int out_size)
{
    const float* in1  = (const float*)d_in[0];
    const float* flow = (const float*)d_in[1];
    float*       out  = (float*)d_out;

    dim3 grid(W / TX, H / TY, B);   // 8 x 24 x 4 = 768 blocks
    resample2d_kernel<<<grid, 256>>>(in1, flow, out);
}

// round 5
// speedup vs baseline: 1.2415x; 1.2415x over previous
#include <cuda_runtime.h>
#include <cstdint>

// Resample2d (FlowNet2 bilinear warp), B=4, C=64, H=384, W=512.
//
// R4: smem-tiled gather with cp.async double-buffered channel pipeline.
//   Block = 64x16 output pixels (256 threads, 4 pixels/thread).
//   Tile  = 28x80 input window (halo +-6 rows / +-8 cols), stride-81 padded.
//   While gathering channel c from buffer c&1, channel c+1 streams into the
//   other buffer via cp.async — fill latency hidden, unlike R3.
//   Taps outside the tile (|flow| > halo; ~never for N(0,1)) use an exact
//   global-memory fallback.

static constexpr int B = 4;
static constexpr int C = 64;
static constexpr int H = 384;
static constexpr int W = 512;
static constexpr int HW = H * W;

static constexpr int TX = 64;
static constexpr int TY = 16;
static constexpr int HUP = 6;        // halo rows above
static constexpr int TROWS = 28;     // 16 + 6 + 6
static constexpr int HL = 8;         // halo cols left
static constexpr int TCOLS = 80;     // 64 + 8 + 8
static constexpr int TS = 81;        // padded smem row stride
static constexpr int TELEMS = TROWS * TS;             // 2268
static constexpr int FILL_IT = (TELEMS + 255) / 256;  // 9

__device__ __forceinline__ int iclamp(int v, int lo, int hi) {
    return min(max(v, lo), hi);
}

__device__ __forceinline__ void cp_async4(uint32_t dst, const float* src) {
    asm volatile("cp.async.ca.shared.global [%0], [%1], 4;" :: "r"(dst), "l"(src));
}
__device__ __forceinline__ void cp_commit() {
    asm volatile("cp.async.commit_group;" ::: "memory");
}
template <int N>
__device__ __forceinline__ void cp_wait() {
    asm volatile("cp.async.wait_group %0;" :: "n"(N) : "memory");
}

__global__ __launch_bounds__(256, 6) void resample2d_kernel(
    const float* __restrict__ in1,
    const float* __restrict__ flow,
    float* __restrict__ out)
{
    __shared__ float tile[2][TELEMS];

    int tid = threadIdx.x;
    int xb = blockIdx.x * TX;
    int yb = blockIdx.y * TY;
    int bz = blockIdx.z;

    int x  = xb + (tid & 63);
    int ry = tid >> 6;                // 0..3

    // ---- precompute clamped global source indices for the tile fill ----
    int sidx[FILL_IT];
    #pragma unroll
    for (int k = 0; k < FILL_IT; ++k) {
        int e  = tid + k * 256;
        int r  = e / TS;
        int cc = e - r * TS;
        int gy = iclamp(yb - HUP + r, 0, H - 1);
        int gx = iclamp(xb - HL + cc, 0, W - 1);
        sidx[k] = (e < TELEMS) ? (gy * W + gx) : 0;
    }
    uint32_t sm0 = (uint32_t)__cvta_generic_to_shared(&tile[0][0]);
    uint32_t sm1 = (uint32_t)__cvta_generic_to_shared(&tile[1][0]);

    // ---- per-pixel flow preamble (4 pixels per thread) ----
    float fa[4], fbw[4];
    unsigned pk0[4], pk1[4];
    int fbmask = 0;
    int opix0 = (yb + ry) * W + x;    // pixel p at opix0 + p*4*W

    const float* fptr = flow + (size_t)bz * 2 * HW;
    #pragma unroll
    for (int p = 0; p < 4; ++p) {
        int y   = yb + ry + 4 * p;
        int pix = y * W + x;
        float dx = fptr[pix];
        float dy = fptr[HW + pix];

        float xf = (float)x + dx;
        float yf = (float)y + dy;
        float x0f = floorf(xf);
        float y0f = floorf(yf);
        fa[p]  = xf - x0f;
        fbw[p] = yf - y0f;

        int x0i = (int)x0f;
        int y0i = (int)y0f;
        int x0 = iclamp(x0i,     0, W - 1);
        int x1 = iclamp(x0i + 1, 0, W - 1);
        int y0 = iclamp(y0i,     0, H - 1);
        int y1 = iclamp(y0i + 1, 0, H - 1);

        int tc0 = x0 - (xb - HL);
        int tc1 = x1 - (xb - HL);
        int tr0 = y0 - (yb - HUP);
        int tr1 = y1 - (yb - HUP);

        bool ok = (tc0 >= 0) & (tc1 < TCOLS) & (tr0 >= 0) & (tr1 < TROWS);
        if (ok) {
            pk0[p] = (unsigned)(tr0 * TS + tc0) | ((unsigned)(tr0 * TS + tc1) << 16);
            pk1[p] = (unsigned)(tr1 * TS + tc0) | ((unsigned)(tr1 * TS + tc1) << 16);
        } else {
            fbmask |= 1 << p;
            pk0[p] = (unsigned)(y0 * W + x0);                        // global base
            pk1[p] = (unsigned)(x1 - x0) | ((unsigned)(y1 - y0) << 1); // dxi,dyi
        }
    }

    const float* bin  = in1 + (size_t)bz * C * HW;
    float*       bout = out + (size_t)bz * C * HW;

    // ---- prologue: fill buffer 0 with channel 0 ----
    {
        const float* src = bin;
        #pragma unroll
        for (int k = 0; k < FILL_IT; ++k) {
            int e = tid + k * 256;
            if (e < TELEMS) cp_async4(sm0 + e * 4, src + sidx[k]);
        }
        cp_commit();
    }

    for (int c = 0; c < C; ++c) {
        // issue fill for next channel into the other buffer
        if (c + 1 < C) {
            const float* nsrc = bin + (size_t)(c + 1) * HW;
            uint32_t dstb = ((c + 1) & 1) ? sm1 : sm0;
            #pragma unroll
            for (int k = 0; k < FILL_IT; ++k) {
                int e = tid + k * 256;
                if (e < TELEMS) cp_async4(dstb + e * 4, nsrc + sidx[k]);
            }
            cp_commit();
            cp_wait<1>();   // channel c's fill complete
        } else {
            cp_wait<0>();
        }
        __syncthreads();

        const float* tl  = tile[c & 1];
        const float* src = bin + (size_t)c * HW;
        float*       dst = bout + (size_t)c * HW;

        #pragma unroll
        for (int p = 0; p < 4; ++p) {
            float a  = fa[p];
            float bw = fbw[p];
            float w00 = (1.0f - a) * (1.0f - bw);
            float w10 = a * (1.0f - bw);
            float w01 = (1.0f - a) * bw;
            float w11 = a * bw;

            float res;
            if (!((fbmask >> p) & 1)) {
                int t00 = pk0[p] & 0xffff;
                int t10 = pk0[p] >> 16;
                int t01 = pk1[p] & 0xffff;
                int t11 = pk1[p] >> 16;
                res = w00 * tl[t00] + w10 * tl[t10]
                    + w01 * tl[t01] + w11 * tl[t11];
            } else {
                int g00 = (int)pk0[p];
                int dxi = pk1[p] & 1;
                int dyi = (pk1[p] >> 1) & 1;
                const float* gp = src + g00;
                res = w00 * __ldg(gp)
                    + w10 * __ldg(gp + dxi)
                    + w01 * __ldg(gp + dyi * W)
                    + w11 * __ldg(gp + dyi * W + dxi);
            }
            dst[opix0 + p * 4 * W] = res;
        }
        __syncthreads();   // protect buffer c&1 before its refill at c+2
    }
}

extern "C" void kernel_launch(void* const* d_in, const int* in_sizes, int n_in,
                              void* d_out, int out_size)
{
    const float* in1  = (const float*)d_in[0];
    const float* flow = (const float*)d_in[1];
    float*       out  = (float*)d_out;

    dim3 grid(W / TX, H / TY, B);   // 8 x 24 x 4 = 768 blocks
    resample2d_kernel<<<grid, 256>>>(in1, flow, out);
}

// round 6
// speedup vs baseline: 2.0453x; 1.6475x over previous
#include <cuda_runtime.h>

// Resample2d (FlowNet2 bilinear warp), fixed shape B=4, C=64, H=384, W=512.
//
// R5: direct per-pixel kernel (R1 structure) with the two x-taps of each row
// merged into a single aligned float2 load at xe = x0 & ~1. Covers both taps
// unless x0 is odd and x1 = x0+1 (then one predicated scalar fallback at
// xe+2). Bilinear weights fold into 3 column coefficients + row lerp, all
// computed once per pixel and reused across the 64 channels.

static constexpr int B = 4;
static constexpr int C = 64;
static constexpr int H = 384;
static constexpr int W = 512;
static constexpr int HW = H * W;
static constexpr int NPIX = B * H * W;

__global__ __launch_bounds__(256, 6) void resample2d_kernel(
    const float* __restrict__ in1,
    const float* __restrict__ flow,
    float* __restrict__ out)
{
    int idx = blockIdx.x * blockDim.x + threadIdx.x;
    if (idx >= NPIX) return;

    int x = idx & (W - 1);          // W = 512 = 2^9
    int t = idx >> 9;               // b*H + y
    int y = t % H;
    int b = t / H;

    int pix = y * W + x;
    const float* fptr = flow + (size_t)b * 2 * HW;
    float dx = fptr[pix];
    float dy = fptr[HW + pix];

    float xf = (float)x + dx;
    float yf = (float)y + dy;
    float x0f = floorf(xf);
    float y0f = floorf(yf);
    float a  = xf - x0f;            // frac x
    float bw = yf - y0f;            // frac y

    int x0i = (int)x0f;
    int y0i = (int)y0f;
    int x0 = min(max(x0i,     0), W - 1);
    int x1 = min(max(x0i + 1, 0), W - 1);
    int y0 = min(max(y0i,     0), H - 1);
    int y1 = min(max(y0i + 1, 0), H - 1);

    int xe = x0 & ~1;               // aligned float2 window base
    int e0 = x0 - xe;               // 0 or 1
    int e1 = x1 - xe;               // 0, 1, or 2

    // Column weights for window components and the (rare) fallback column.
    float one_m_a = 1.0f - a;
    float clo = (e0 == 0 ? one_m_a : 0.0f) + (e1 == 0 ? a : 0.0f);
    float chi = (e0 == 1 ? one_m_a : 0.0f) + (e1 == 1 ? a : 0.0f);
    float cfb = (e1 == 2) ? a : 0.0f;

    float r0w = 1.0f - bw;          // row y0 weight
    float r1w = bw;                 // row y1 weight

    const float* base = in1 + (size_t)b * C * HW;
    const float* r0p = base + y0 * W + xe;   // float2-aligned
    const float* r1p = base + y1 * W + xe;
    float* o = out + (size_t)b * C * HW + pix;

    #pragma unroll 4
    for (int c = 0; c < C; ++c) {
        size_t off = (size_t)c * HW;
        float2 q0 = __ldg((const float2*)(r0p + off));
        float2 q1 = __ldg((const float2*)(r1p + off));

        float row0 = clo * q0.x + chi * q0.y;
        float row1 = clo * q1.x + chi * q1.y;
        if (cfb != 0.0f) {
            row0 += cfb * __ldg(r0p + off + 2);
            row1 += cfb * __ldg(r1p + off + 2);
        }
        __stcs(o + off, r0w * row0 + r1w * row1);
    }
}

extern "C" void kernel_launch(void* const* d_in, const int* in_sizes, int n_in,
                              void* d_out, int out_size)
{
    const float* in1  = (const float*)d_in[0];
    const float* flow = (const float*)d_in[1];
    float*       out  = (float*)d_out;

    int threads = 256;
    int blocks = (NPIX + threads - 1) / threads;
    resample2d_kernel<<<blocks, threads>>>(in1, flow, out);
}

// round 7
// speedup vs baseline: 2.6365x; 1.2890x over previous
#include <cuda_runtime.h>

// Resample2d (FlowNet2 bilinear warp), fixed shape B=4, C=64, H=384, W=512.
//
// R6: R1 structure (scalar gathers — proven cheapest L1 currency for this
// scattered pattern) with deeper unrolling (8) for more memory-level
// parallelism and a pointer-increment channel loop. One thread per output
// pixel; flow, weights and the 4 clamped tap offsets computed once and
// reused across all 64 channels.

static constexpr int B = 4;
static constexpr int C = 64;
static constexpr int H = 384;
static constexpr int W = 512;
static constexpr int HW = H * W;
static constexpr int NPIX = B * H * W;

__global__ __launch_bounds__(256) void resample2d_kernel(
    const float* __restrict__ in1,
    const float* __restrict__ flow,
    float* __restrict__ out)
{
    int idx = blockIdx.x * blockDim.x + threadIdx.x;
    if (idx >= NPIX) return;

    int x = idx & (W - 1);          // W = 512 = 2^9
    int t = idx >> 9;               // b*H + y
    int y = t % H;
    int b = t / H;

    int pix = y * W + x;
    const float* fptr = flow + (size_t)b * 2 * HW;
    float dx = fptr[pix];
    float dy = fptr[HW + pix];

    float xf = (float)x + dx;
    float yf = (float)y + dy;
    float x0f = floorf(xf);
    float y0f = floorf(yf);
    float a  = xf - x0f;            // frac x
    float bw = yf - y0f;            // frac y

    int x0i = (int)x0f;
    int y0i = (int)y0f;
    int x0 = min(max(x0i,     0), W - 1);
    int x1 = min(max(x0i + 1, 0), W - 1);
    int y0 = min(max(y0i,     0), H - 1);
    int y1 = min(max(y0i + 1, 0), H - 1);

    float w00 = (1.0f - a) * (1.0f - bw);
    float w10 = a * (1.0f - bw);
    float w01 = (1.0f - a) * bw;
    float w11 = a * bw;

    const float* base = in1 + (size_t)b * C * HW;
    const float* p00 = base + y0 * W + x0;
    const float* p10 = base + y0 * W + x1;
    const float* p01 = base + y1 * W + x0;
    const float* p11 = base + y1 * W + x1;
    float* o = out + (size_t)b * C * HW + pix;

    #pragma unroll 8
    for (int c = 0; c < C; ++c) {
        float v00 = __ldg(p00);
        float v10 = __ldg(p10);
        float v01 = __ldg(p01);
        float v11 = __ldg(p11);
        *o = w00 * v00 + w10 * v10 + w01 * v01 + w11 * v11;
        p00 += HW; p10 += HW; p01 += HW; p11 += HW; o += HW;
    }
}

extern "C" void kernel_launch(void* const* d_in, const int* in_sizes, int n_in,
                              void* d_out, int out_size)
{
    const float* in1  = (const float*)d_in[0];
    const float* flow = (const float*)d_in[1];
    float*       out  = (float*)d_out;

    int threads = 256;
    int blocks = (NPIX + threads - 1) / threads;
    resample2d_kernel<<<blocks, threads>>>(in1, flow, out);
}